// round 15
// baseline (speedup 1.0000x reference)
#include <cuda_runtime.h>
#include <cuda_fp16.h>
#include <cstdint>
#include <math.h>

// Problem constants
#define T_TOK 4096
#define H_DIM 2048
#define E_NUM 32
#define I_DIM 1024
#define TOPK  8
#define P_NUM (T_TOK * TOPK)
#define W_ELEMS ((size_t)E_NUM * H_DIM * I_DIM)

// ---------------- scratch ----------------
__device__ int    g_topk_ids[P_NUM];
__device__ float  g_topk_w[P_NUM];
__device__ int    g_cnt[E_NUM];
__device__ int    g_pos[E_NUM];
__device__ int    g_off[E_NUM + 1];
__device__ int    g_slot_token[P_NUM];
__device__ float  g_slot_w[P_NUM];
__device__ int    g_pair2slot[P_NUM];
__device__ __half g_hbuf_h[(size_t)P_NUM * I_DIM];
__device__ __half g_dbuf_h[(size_t)P_NUM * H_DIM];
__device__ __half g_x_h[(size_t)T_TOK * H_DIM];
__device__ __half g_wg_h[W_ELEMS];   // [E][I][H]
__device__ __half g_wu_h[W_ELEMS];   // [E][I][H]
__device__ __half g_wd_h[W_ELEMS];   // [E][H][I]

// ---------------- helpers ----------------
__device__ __forceinline__ void mma16(float c[4], const uint32_t a[4], const uint32_t b[2]) {
    asm volatile(
        "mma.sync.aligned.m16n8k16.row.col.f32.f16.f16.f32 "
        "{%0,%1,%2,%3}, {%4,%5,%6,%7}, {%8,%9}, {%0,%1,%2,%3};\n"
        : "+f"(c[0]), "+f"(c[1]), "+f"(c[2]), "+f"(c[3])
        : "r"(a[0]), "r"(a[1]), "r"(a[2]), "r"(a[3]), "r"(b[0]), "r"(b[1]));
}

__device__ __forceinline__ void ldsm4(uint32_t& r0, uint32_t& r1, uint32_t& r2,
                                      uint32_t& r3, uint32_t addr) {
    asm volatile("ldmatrix.sync.aligned.m8n8.x4.shared.b16 {%0,%1,%2,%3}, [%4];"
                 : "=r"(r0), "=r"(r1), "=r"(r2), "=r"(r3) : "r"(addr));
}

__device__ __forceinline__ void cpa16(uint32_t saddr, const void* g) {
    asm volatile("cp.async.cg.shared.global [%0], [%1], 16;" :: "r"(saddr), "l"(g));
}
#define CP_COMMIT() asm volatile("cp.async.commit_group;")
#define CP_WAIT(N)  asm volatile("cp.async.wait_group %0;" :: "n"(N))

__device__ __forceinline__ float silu(float x) {
    return x * (1.0f / (1.0f + __expf(-x)));
}

__device__ __forceinline__ uint2 pack4h(float a, float b, float c, float d) {
    __half2 lo = __floats2half2_rn(a, b);
    __half2 hi = __floats2half2_rn(c, d);
    uint2 r;
    r.x = *(uint32_t*)&lo;
    r.y = *(uint32_t*)&hi;
    return r;
}

// ---------------- kernel 1: router + x->fp16 ----------------
__global__ __launch_bounds__(256) void k_router(const float* __restrict__ x,
                                                const float* __restrict__ gw,
                                                float* __restrict__ out, int write_ids) {
    __shared__ float s_gw[64 * E_NUM];
    int tid  = threadIdx.x;
    int wid  = tid >> 5, lane = tid & 31;
    int tok  = blockIdx.x * 8 + wid;

    const float* xr = x + (size_t)tok * H_DIM;
    float acc = 0.0f;
    for (int h0 = 0; h0 < H_DIM; h0 += 64) {
#pragma unroll
        for (int i = 0; i < 8; i++) s_gw[tid + i * 256] = gw[h0 * E_NUM + tid + i * 256];
        __syncthreads();
#pragma unroll 16
        for (int hh = 0; hh < 64; hh++) acc += xr[h0 + hh] * s_gw[hh * E_NUM + lane];
        __syncthreads();
    }

    {
        __half* xh = g_x_h + (size_t)tok * H_DIM;
        for (int h = lane * 4; h < H_DIM; h += 128) {
            float4 v = *(const float4*)&xr[h];
            *(uint2*)&xh[h] = pack4h(v.x, v.y, v.z, v.w);
        }
    }

    float m = acc;
#pragma unroll
    for (int o = 16; o; o >>= 1) m = fmaxf(m, __shfl_xor_sync(0xffffffffu, m, o));
    float p = expf(acc - m);
    float s = p;
#pragma unroll
    for (int o = 16; o; o >>= 1) s += __shfl_xor_sync(0xffffffffu, s, o);
    float score = p / s;

    float val = score;
    int   ids[TOPK];
    float ws[TOPK];
    float wsum = 0.0f;
#pragma unroll
    for (int j = 0; j < TOPK; j++) {
        float bv = val;
        int   bi = lane;
#pragma unroll
        for (int o = 16; o; o >>= 1) {
            float ov = __shfl_xor_sync(0xffffffffu, bv, o);
            int   oi = __shfl_xor_sync(0xffffffffu, bi, o);
            if (ov > bv || (ov == bv && oi < bi)) { bv = ov; bi = oi; }
        }
        ids[j] = bi; ws[j] = bv; wsum += bv;
        if (lane == bi) val = -1.0f;
    }

    if (lane == 0) {
        float inv = 1.0f / wsum;
#pragma unroll
        for (int j = 0; j < TOPK; j++) {
            g_topk_ids[tok * TOPK + j] = ids[j];
            g_topk_w[tok * TOPK + j]   = ws[j] * inv;
            atomicAdd(&g_cnt[ids[j]], 1);
            if (write_ids)
                out[(size_t)T_TOK * H_DIM + tok * TOPK + j] = (float)ids[j];
        }
    }
}

// ---------------- kernel 2: fused scan + scatter ----------------
__global__ __launch_bounds__(1024) void k_scan_scatter() {
    int tid = threadIdx.x;
    if (tid == 0) {
        int acc = 0;
        for (int e = 0; e < E_NUM; e++) { g_off[e] = acc; g_pos[e] = acc; acc += g_cnt[e]; }
        g_off[E_NUM] = acc;
    }
    __syncthreads();
    for (int pp = tid; pp < P_NUM; pp += 1024) {
        int e = g_topk_ids[pp];
        int slot = atomicAdd(&g_pos[e], 1);
        g_slot_token[slot] = pp >> 3;
        g_slot_w[slot]     = g_topk_w[pp];
        g_pair2slot[pp]    = slot;
    }
}

// ---------------- vectorized transposing cvt (dual) ----------------
__global__ __launch_bounds__(256) void k_cvt_t2(const float* __restrict__ s1,
                                                const float* __restrict__ s2,
                                                __half* __restrict__ d1,
                                                __half* __restrict__ d2, int R, int C) {
    __shared__ float t1[32][36];
    __shared__ float t2[32][36];
    int e  = blockIdx.z;
    int c0 = blockIdx.x * 32, r0 = blockIdx.y * 32;
    size_t eo = (size_t)e * R * C;
    int tid = threadIdx.x;
    int lr = tid >> 3, lc = (tid & 7) * 4;
    {
        float4 v1 = *(const float4*)&s1[eo + (size_t)(r0 + lr) * C + c0 + lc];
        float4 v2 = *(const float4*)&s2[eo + (size_t)(r0 + lr) * C + c0 + lc];
        *(float4*)&t1[lr][lc] = v1;
        *(float4*)&t2[lr][lc] = v2;
    }
    __syncthreads();
    int sc = tid >> 3, sr = (tid & 7) * 4;
    {
        uint2 v1 = pack4h(t1[sr][sc], t1[sr+1][sc], t1[sr+2][sc], t1[sr+3][sc]);
        uint2 v2 = pack4h(t2[sr][sc], t2[sr+1][sc], t2[sr+2][sc], t2[sr+3][sc]);
        *(uint2*)&d1[eo + (size_t)(c0 + sc) * R + r0 + sr] = v1;
        *(uint2*)&d2[eo + (size_t)(c0 + sc) * R + r0 + sr] = v2;
    }
}

__global__ __launch_bounds__(256) void k_cvt_t1(const float* __restrict__ s1,
                                                __half* __restrict__ d1, int R, int C) {
    __shared__ float t1[32][36];
    int e  = blockIdx.z;
    int c0 = blockIdx.x * 32, r0 = blockIdx.y * 32;
    size_t eo = (size_t)e * R * C;
    int tid = threadIdx.x;
    int lr = tid >> 3, lc = (tid & 7) * 4;
    *(float4*)&t1[lr][lc] = *(const float4*)&s1[eo + (size_t)(r0 + lr) * C + c0 + lc];
    __syncthreads();
    int sc = tid >> 3, sr = (tid & 7) * 4;
    uint2 v1 = pack4h(t1[sr][sc], t1[sr+1][sc], t1[sr+2][sc], t1[sr+3][sc]);
    *(uint2*)&d1[eo + (size_t)(c0 + sc) * R + r0 + sr] = v1;
}

// ================= GEMM tiling (halves) =================
#define AH_STRIDE 72                   // 64 + 8 pad (144 B rows)
#define A_BYTES   (128 * AH_STRIDE * 2)   // 18432 B
#define BG_BYTES  (64  * AH_STRIDE * 2)   // 9216 B
// gemmA slot: A | Bg | Bu = 36864 B. gemmB slot: A | B(128 rows) = 36864 B.
#define SLOT_BYTES 36864
#define NSTAGE 3

// ================= kernel 4: gate+up GEMM + SwiGLU (fp16 mma, 3-stage) =================
__global__ __launch_bounds__(256, 2) void k_gemmA(const __half* __restrict__ x,
                                                  const __half* __restrict__ wgate,
                                                  const __half* __restrict__ wup) {
    int e   = blockIdx.z;
    int cnt = g_cnt[e];
    int m0  = blockIdx.y * 128;
    if (m0 >= cnt) return;
    int n0   = blockIdx.x * 64;
    int base = g_off[e];
    int tid  = threadIdx.x;

    extern __shared__ __half smem[];
    uint32_t sbase = (uint32_t)__cvta_generic_to_shared(smem);

    __shared__ int s_tok[128];
    if (tid < 128) {
        int m = m0 + tid;
        s_tok[tid] = g_slot_token[base + ((m < cnt) ? m : 0)];
    }
    __syncthreads();

    const __half* wgb = wgate + ((size_t)e * I_DIM + n0) * H_DIM;
    const __half* wub = wup   + ((size_t)e * I_DIM + n0) * H_DIM;

    int c8 = tid & 7, r32 = tid >> 3;

    const int NT = H_DIM / 64;  // 32

    auto load_stage = [&](int t, int s) {
        int k0 = t * 64;
        uint32_t ab = sbase + s * SLOT_BYTES;
        uint32_t gb = ab + A_BYTES;
        uint32_t ub = gb + BG_BYTES;
#pragma unroll
        for (int i = 0; i < 4; i++) {
            int r = r32 + i * 32;
            cpa16(ab + (uint32_t)(r * AH_STRIDE + c8 * 8) * 2u,
                  x + (size_t)s_tok[r] * H_DIM + k0 + c8 * 8);
        }
#pragma unroll
        for (int i = 0; i < 2; i++) {
            int r = r32 + i * 32;
            uint32_t so = (uint32_t)(r * AH_STRIDE + c8 * 8) * 2u;
            cpa16(gb + so, wgb + (size_t)r * H_DIM + k0 + c8 * 8);
            cpa16(ub + so, wub + (size_t)r * H_DIM + k0 + c8 * 8);
        }
        CP_COMMIT();
    };

    int wid = tid >> 5, lane = tid & 31;
    int wm = (wid & 3) * 32, wn = (wid >> 2) * 32;
    int gid = lane >> 2, tig = lane & 3;

    int a_row  = lane & 15, a_col = (lane >> 4) << 3;
    int b_rowo = ((lane >> 4) << 3) + (lane & 7);
    int b_colo = ((lane >> 3) & 1) << 3;

    float cg[2][4][4], cu[2][4][4];
#pragma unroll
    for (int i = 0; i < 2; i++)
#pragma unroll
        for (int j = 0; j < 4; j++)
#pragma unroll
            for (int q = 0; q < 4; q++) { cg[i][j][q] = 0.0f; cu[i][j][q] = 0.0f; }

    load_stage(0, 0);
    load_stage(1, 1);

    int sl = 2, sc = 0;
    for (int t = 0; t < NT; t++) {
        CP_WAIT(1);          // load(t) done (tail stays correct via empty commits)
        __syncthreads();
        if (t + 2 < NT) {
            load_stage(t + 2, sl);
            if (++sl == NSTAGE) sl = 0;
        } else {
            CP_COMMIT();     // empty group keeps wait_group accounting uniform
        }

        uint32_t sA = sbase + sc * SLOT_BYTES;
        uint32_t sG = sA + A_BYTES;
        uint32_t sU = sG + BG_BYTES;
        if (++sc == NSTAGE) sc = 0;

#pragma unroll
        for (int kf = 0; kf < 64; kf += 16) {
            uint32_t a[2][4], bg[4][2], bu[4][2];
#pragma unroll
            for (int mf = 0; mf < 2; mf++) {
                uint32_t addr = sA + (uint32_t)((wm + mf * 16 + a_row) * AH_STRIDE
                                                + kf + a_col) * 2u;
                ldsm4(a[mf][0], a[mf][1], a[mf][2], a[mf][3], addr);
            }
#pragma unroll
            for (int p = 0; p < 2; p++) {
                uint32_t so = (uint32_t)((wn + p * 16 + b_rowo) * AH_STRIDE
                                         + kf + b_colo) * 2u;
                ldsm4(bg[2*p][0], bg[2*p][1], bg[2*p+1][0], bg[2*p+1][1], sG + so);
                ldsm4(bu[2*p][0], bu[2*p][1], bu[2*p+1][0], bu[2*p+1][1], sU + so);
            }
#pragma unroll
            for (int mf = 0; mf < 2; mf++)
#pragma unroll
                for (int nf = 0; nf < 4; nf++) {
                    mma16(cg[mf][nf], a[mf], bg[nf]);
                    mma16(cu[mf][nf], a[mf], bu[nf]);
                }
        }
    }

    // epilogue: h = silu(g)*u -> fp16 hbuf
#pragma unroll
    for (int mf = 0; mf < 2; mf++)
#pragma unroll
        for (int nf = 0; nf < 4; nf++) {
            int col = n0 + wn + nf * 8 + 2 * tig;
            int r1 = wm + mf * 16 + gid;
            int r2 = r1 + 8;
            int m1 = m0 + r1, m2 = m0 + r2;
            if (m1 < cnt) {
                __half2 v = __floats2half2_rn(silu(cg[mf][nf][0]) * cu[mf][nf][0],
                                              silu(cg[mf][nf][1]) * cu[mf][nf][1]);
                *(__half2*)&g_hbuf_h[(size_t)(base + m1) * I_DIM + col] = v;
            }
            if (m2 < cnt) {
                __half2 v = __floats2half2_rn(silu(cg[mf][nf][2]) * cu[mf][nf][2],
                                              silu(cg[mf][nf][3]) * cu[mf][nf][3]);
                *(__half2*)&g_hbuf_h[(size_t)(base + m2) * I_DIM + col] = v;
            }
        }
}

// ================= kernel 5: down GEMM weighted (fp16 mma, 3-stage) =================
__global__ __launch_bounds__(256, 2) void k_gemmB(const __half* __restrict__ wdown) {
    int e   = blockIdx.z;
    int cnt = g_cnt[e];
    int m0  = blockIdx.y * 128;
    if (m0 >= cnt) return;
    int n0   = blockIdx.x * 128;
    int base = g_off[e];
    int tid  = threadIdx.x;

    extern __shared__ __half smem[];
    uint32_t sbase = (uint32_t)__cvta_generic_to_shared(smem);

    const __half* wb = wdown + ((size_t)e * H_DIM + n0) * I_DIM;

    int c8 = tid & 7, r32 = tid >> 3;

    const int NT = I_DIM / 64;  // 16

    auto load_stage = [&](int t, int s) {
        int k0 = t * 64;
        uint32_t ab = sbase + s * SLOT_BYTES;
        uint32_t bb = ab + A_BYTES;
#pragma unroll
        for (int i = 0; i < 4; i++) {
            int r = r32 + i * 32;
            int m = m0 + r;
            int slot = base + ((m < cnt) ? m : (cnt - 1));
            cpa16(ab + (uint32_t)(r * AH_STRIDE + c8 * 8) * 2u,
                  &g_hbuf_h[(size_t)slot * I_DIM + k0 + c8 * 8]);
        }
#pragma unroll
        for (int i = 0; i < 4; i++) {
            int r = r32 + i * 32;
            cpa16(bb + (uint32_t)(r * AH_STRIDE + c8 * 8) * 2u,
                  wb + (size_t)r * I_DIM + k0 + c8 * 8);
        }
        CP_COMMIT();
    };

    int wid = tid >> 5, lane = tid & 31;
    int wm = (wid & 3) * 32, wn = (wid >> 2) * 64;
    int gid = lane >> 2, tig = lane & 3;

    int a_row  = lane & 15, a_col = (lane >> 4) << 3;
    int b_rowo = ((lane >> 4) << 3) + (lane & 7);
    int b_colo = ((lane >> 3) & 1) << 3;

    float cc[2][8][4];
#pragma unroll
    for (int i = 0; i < 2; i++)
#pragma unroll
        for (int j = 0; j < 8; j++)
#pragma unroll
            for (int q = 0; q < 4; q++) cc[i][j][q] = 0.0f;

    load_stage(0, 0);
    load_stage(1, 1);

    int sl = 2, sc = 0;
    for (int t = 0; t < NT; t++) {
        CP_WAIT(1);
        __syncthreads();
        if (t + 2 < NT) {
            load_stage(t + 2, sl);
            if (++sl == NSTAGE) sl = 0;
        } else {
            CP_COMMIT();
        }

        uint32_t sA = sbase + sc * SLOT_BYTES;
        uint32_t sB = sA + A_BYTES;
        if (++sc == NSTAGE) sc = 0;

#pragma unroll
        for (int kf = 0; kf < 64; kf += 16) {
            uint32_t a[2][4], b[8][2];
#pragma unroll
            for (int mf = 0; mf < 2; mf++) {
                uint32_t addr = sA + (uint32_t)((wm + mf * 16 + a_row) * AH_STRIDE
                                                + kf + a_col) * 2u;
                ldsm4(a[mf][0], a[mf][1], a[mf][2], a[mf][3], addr);
            }
#pragma unroll
            for (int p = 0; p < 4; p++) {
                uint32_t so = (uint32_t)((wn + p * 16 + b_rowo) * AH_STRIDE
                                         + kf + b_colo) * 2u;
                ldsm4(b[2*p][0], b[2*p][1], b[2*p+1][0], b[2*p+1][1], sB + so);
            }
#pragma unroll
            for (int mf = 0; mf < 2; mf++)
#pragma unroll
                for (int nf = 0; nf < 8; nf++) mma16(cc[mf][nf], a[mf], b[nf]);
        }
    }

#pragma unroll
    for (int mf = 0; mf < 2; mf++) {
        int r1 = wm + mf * 16 + gid;
        int r2 = r1 + 8;
        int m1 = m0 + r1, m2 = m0 + r2;
        float w1 = (m1 < cnt) ? g_slot_w[base + m1] : 0.0f;
        float w2 = (m2 < cnt) ? g_slot_w[base + m2] : 0.0f;
#pragma unroll
        for (int nf = 0; nf < 8; nf++) {
            int col = n0 + wn + nf * 8 + 2 * tig;
            if (m1 < cnt) {
                __half2 v = __floats2half2_rn(cc[mf][nf][0] * w1, cc[mf][nf][1] * w1);
                *(__half2*)&g_dbuf_h[(size_t)(base + m1) * H_DIM + col] = v;
            }
            if (m2 < cnt) {
                __half2 v = __floats2half2_rn(cc[mf][nf][2] * w2, cc[mf][nf][3] * w2);
                *(__half2*)&g_dbuf_h[(size_t)(base + m2) * H_DIM + col] = v;
            }
        }
    }
}

// ---------------- kernel 6: combine ----------------
__global__ void k_reduce(float* __restrict__ out) {
    int idx4 = blockIdx.x * blockDim.x + threadIdx.x;
    int t  = idx4 >> 9;
    int h4 = idx4 & 511;
    const int* ps = &g_pair2slot[t * TOPK];
    float4 s = make_float4(0.f, 0.f, 0.f, 0.f);
#pragma unroll
    for (int k = 0; k < TOPK; k++) {
        uint2 raw = *(const uint2*)&g_dbuf_h[(size_t)ps[k] * H_DIM + h4 * 4];
        __half2 p0 = *(__half2*)&raw.x;
        __half2 p1 = *(__half2*)&raw.y;
        float2 f0 = __half22float2(p0);
        float2 f1 = __half22float2(p1);
        s.x += f0.x; s.y += f0.y; s.z += f1.x; s.w += f1.y;
    }
    *(float4*)&out[(size_t)idx4 * 4] = s;
}

// ---------------- launch ----------------
extern "C" void kernel_launch(void* const* d_in, const int* in_sizes, int n_in,
                              void* d_out, int out_size) {
    const float* x  = (const float*)d_in[0];
    const float* gw = (const float*)d_in[1];
    const float* wg = (const float*)d_in[2];
    const float* wu = (const float*)d_in[3];
    const float* wd = (const float*)d_in[4];
    float* out = (float*)d_out;

    int write_ids = (out_size >= T_TOK * H_DIM + P_NUM) ? 1 : 0;

    const int smemG = NSTAGE * SLOT_BYTES;   // 110592 B -> 2 CTAs/SM
    cudaFuncSetAttribute(k_gemmA, cudaFuncAttributeMaxDynamicSharedMemorySize, smemG);
    cudaFuncSetAttribute(k_gemmB, cudaFuncAttributeMaxDynamicSharedMemorySize, smemG);

    int* cnt_p;
    cudaGetSymbolAddress((void**)&cnt_p, g_cnt);
    cudaMemsetAsync(cnt_p, 0, E_NUM * sizeof(int));

    __half* wg_h; __half* wu_h; __half* wd_h; __half* x_h;
    cudaGetSymbolAddress((void**)&wg_h, g_wg_h);
    cudaGetSymbolAddress((void**)&wu_h, g_wu_h);
    cudaGetSymbolAddress((void**)&wd_h, g_wd_h);
    cudaGetSymbolAddress((void**)&x_h,  g_x_h);

    k_router<<<T_TOK / 8, 256>>>(x, gw, out, write_ids);            // L1
    k_scan_scatter<<<1, 1024>>>();                                  // L2

    {
        dim3 g1(I_DIM / 32, H_DIM / 32, E_NUM);
        k_cvt_t2<<<g1, 256>>>(wg, wu, wg_h, wu_h, H_DIM, I_DIM);    // L3
    }

    dim3 ga(I_DIM / 64, T_TOK / 128, E_NUM);
    k_gemmA<<<ga, 256, smemG>>>(x_h, wg_h, wu_h);                   // L4 <- profile target

    {
        dim3 g2(H_DIM / 32, I_DIM / 32, E_NUM);
        k_cvt_t1<<<g2, 256>>>(wd, wd_h, I_DIM, H_DIM);              // L5
    }

    dim3 gb(H_DIM / 128, T_TOK / 128, E_NUM);
    k_gemmB<<<gb, 256, smemG>>>(wd_h);                              // L6

    k_reduce<<<(T_TOK * H_DIM / 4) / 256, 256>>>(out);              // L7
}

// round 16
// speedup vs baseline: 1.0522x; 1.0522x over previous
#include <cuda_runtime.h>
#include <cuda_fp16.h>
#include <cstdint>
#include <math.h>

// Problem constants
#define T_TOK 4096
#define H_DIM 2048
#define E_NUM 32
#define I_DIM 1024
#define TOPK  8
#define P_NUM (T_TOK * TOPK)
#define W_ELEMS ((size_t)E_NUM * H_DIM * I_DIM)

// ---------------- scratch ----------------
__device__ int    g_topk_ids[P_NUM];
__device__ float  g_topk_w[P_NUM];
__device__ int    g_cnt[E_NUM];
__device__ int    g_pos[E_NUM];
__device__ int    g_off[E_NUM + 1];
__device__ int    g_slot_token[P_NUM];
__device__ float  g_slot_w[P_NUM];
__device__ int    g_pair2slot[P_NUM];
__device__ __half g_hbuf_h[(size_t)P_NUM * I_DIM];
__device__ __half g_dbuf_h[(size_t)P_NUM * H_DIM];
__device__ __half g_x_h[(size_t)T_TOK * H_DIM];
__device__ __half g_wg_h[W_ELEMS];   // [E][I][H]
__device__ __half g_wu_h[W_ELEMS];   // [E][I][H]
__device__ __half g_wd_h[W_ELEMS];   // [E][H][I]

// ---------------- helpers ----------------
__device__ __forceinline__ void mma16(float c[4], const uint32_t a[4], const uint32_t b[2]) {
    asm volatile(
        "mma.sync.aligned.m16n8k16.row.col.f32.f16.f16.f32 "
        "{%0,%1,%2,%3}, {%4,%5,%6,%7}, {%8,%9}, {%0,%1,%2,%3};\n"
        : "+f"(c[0]), "+f"(c[1]), "+f"(c[2]), "+f"(c[3])
        : "r"(a[0]), "r"(a[1]), "r"(a[2]), "r"(a[3]), "r"(b[0]), "r"(b[1]));
}

__device__ __forceinline__ void ldsm4(uint32_t& r0, uint32_t& r1, uint32_t& r2,
                                      uint32_t& r3, uint32_t addr) {
    asm volatile("ldmatrix.sync.aligned.m8n8.x4.shared.b16 {%0,%1,%2,%3}, [%4];"
                 : "=r"(r0), "=r"(r1), "=r"(r2), "=r"(r3) : "r"(addr));
}

__device__ __forceinline__ void cpa16(uint32_t saddr, const void* g) {
    asm volatile("cp.async.cg.shared.global [%0], [%1], 16;" :: "r"(saddr), "l"(g));
}
#define CP_COMMIT() asm volatile("cp.async.commit_group;")
#define CP_WAIT(N)  asm volatile("cp.async.wait_group %0;" :: "n"(N))

__device__ __forceinline__ float silu(float x) {
    return x * (1.0f / (1.0f + __expf(-x)));
}

__device__ __forceinline__ uint2 pack4h(float a, float b, float c, float d) {
    __half2 lo = __floats2half2_rn(a, b);
    __half2 hi = __floats2half2_rn(c, d);
    uint2 r;
    r.x = *(uint32_t*)&lo;
    r.y = *(uint32_t*)&hi;
    return r;
}

// ================= kernel 1: fused router + x-cvt + wg/wu transposing cvt =========
// blocks [0,512): router (8 tokens each). blocks [512, 512+65536): wg/wu cvt tiles.
#define PRE_ROUTER_BLOCKS 512

__global__ __launch_bounds__(256) void k_pre(const float* __restrict__ x,
                                             const float* __restrict__ gw,
                                             const float* __restrict__ wg,
                                             const float* __restrict__ wu,
                                             float* __restrict__ out, int write_ids) {
    int tid = threadIdx.x;

    if (blockIdx.x >= PRE_ROUTER_BLOCKS) {
        // ---- wg/wu transposing cvt: [E][H][I] f32 -> [E][I][H] fp16 ----
        __shared__ float t1[32][36];
        __shared__ float t2[32][36];
        int idx = blockIdx.x - PRE_ROUTER_BLOCKS;
        int cx = idx & 31;           // I/32 tiles
        int cy = (idx >> 5) & 63;    // H/32 tiles
        int e  = idx >> 11;
        int c0 = cx * 32, r0 = cy * 32;
        size_t eo = (size_t)e * H_DIM * I_DIM;
        int lr = tid >> 3, lc = (tid & 7) * 4;
        {
            float4 v1 = *(const float4*)&wg[eo + (size_t)(r0 + lr) * I_DIM + c0 + lc];
            float4 v2 = *(const float4*)&wu[eo + (size_t)(r0 + lr) * I_DIM + c0 + lc];
            *(float4*)&t1[lr][lc] = v1;
            *(float4*)&t2[lr][lc] = v2;
        }
        __syncthreads();
        int sc = tid >> 3, sr = (tid & 7) * 4;
        {
            uint2 v1 = pack4h(t1[sr][sc], t1[sr+1][sc], t1[sr+2][sc], t1[sr+3][sc]);
            uint2 v2 = pack4h(t2[sr][sc], t2[sr+1][sc], t2[sr+2][sc], t2[sr+3][sc]);
            *(uint2*)&g_wg_h[eo + (size_t)(c0 + sc) * H_DIM + r0 + sr] = v1;
            *(uint2*)&g_wu_h[eo + (size_t)(c0 + sc) * H_DIM + r0 + sr] = v2;
        }
        return;
    }

    // ---- router ----
    __shared__ float s_gw[64 * E_NUM];
    int wid  = tid >> 5, lane = tid & 31;
    int tok  = blockIdx.x * 8 + wid;

    const float* xr = x + (size_t)tok * H_DIM;
    float acc = 0.0f;
    for (int h0 = 0; h0 < H_DIM; h0 += 64) {
#pragma unroll
        for (int i = 0; i < 8; i++) s_gw[tid + i * 256] = gw[h0 * E_NUM + tid + i * 256];
        __syncthreads();
#pragma unroll 16
        for (int hh = 0; hh < 64; hh++) acc += xr[h0 + hh] * s_gw[hh * E_NUM + lane];
        __syncthreads();
    }

    {
        __half* xh = g_x_h + (size_t)tok * H_DIM;
        for (int h = lane * 4; h < H_DIM; h += 128) {
            float4 v = *(const float4*)&xr[h];
            *(uint2*)&xh[h] = pack4h(v.x, v.y, v.z, v.w);
        }
    }

    float m = acc;
#pragma unroll
    for (int o = 16; o; o >>= 1) m = fmaxf(m, __shfl_xor_sync(0xffffffffu, m, o));
    float p = expf(acc - m);
    float s = p;
#pragma unroll
    for (int o = 16; o; o >>= 1) s += __shfl_xor_sync(0xffffffffu, s, o);
    float score = p / s;

    float val = score;
    int   ids[TOPK];
    float ws[TOPK];
    float wsum = 0.0f;
#pragma unroll
    for (int j = 0; j < TOPK; j++) {
        float bv = val;
        int   bi = lane;
#pragma unroll
        for (int o = 16; o; o >>= 1) {
            float ov = __shfl_xor_sync(0xffffffffu, bv, o);
            int   oi = __shfl_xor_sync(0xffffffffu, bi, o);
            if (ov > bv || (ov == bv && oi < bi)) { bv = ov; bi = oi; }
        }
        ids[j] = bi; ws[j] = bv; wsum += bv;
        if (lane == bi) val = -1.0f;
    }

    if (lane == 0) {
        float inv = 1.0f / wsum;
#pragma unroll
        for (int j = 0; j < TOPK; j++) {
            g_topk_ids[tok * TOPK + j] = ids[j];
            g_topk_w[tok * TOPK + j]   = ws[j] * inv;
            atomicAdd(&g_cnt[ids[j]], 1);
            if (write_ids)
                out[(size_t)T_TOK * H_DIM + tok * TOPK + j] = (float)ids[j];
        }
    }
}

// ---------------- kernel 2: fused scan + scatter ----------------
__global__ __launch_bounds__(1024) void k_scan_scatter() {
    int tid = threadIdx.x;
    if (tid == 0) {
        int acc = 0;
        for (int e = 0; e < E_NUM; e++) { g_off[e] = acc; g_pos[e] = acc; acc += g_cnt[e]; }
        g_off[E_NUM] = acc;
    }
    __syncthreads();
    for (int pp = tid; pp < P_NUM; pp += 1024) {
        int e = g_topk_ids[pp];
        int slot = atomicAdd(&g_pos[e], 1);
        g_slot_token[slot] = pp >> 3;
        g_slot_w[slot]     = g_topk_w[pp];
        g_pair2slot[pp]    = slot;
    }
}

// ================= GEMM tiling (halves) =================
#define AH_STRIDE 72
#define A_BYTES   (128 * AH_STRIDE * 2)   // 18432 B
#define BG_BYTES  (64  * AH_STRIDE * 2)   // 9216 B
#define SLOT_BYTES 36864
#define NSTAGE 3
#define GA_BLOCKS 16384                    // gemm part of k_gemmA grid
#define WD_CVT_BLOCKS 16384                // wd cvt part (4 c-tiles each)

// ================= kernel 3: gate+up GEMM + SwiGLU, with wd-cvt tail blocks =====
__global__ __launch_bounds__(256, 2) void k_gemmA(const __half* __restrict__ x,
                                                  const __half* __restrict__ wgate,
                                                  const __half* __restrict__ wup,
                                                  const float* __restrict__ wd_src) {
    extern __shared__ __half smem[];
    int tid  = threadIdx.x;

    if (blockIdx.x >= GA_BLOCKS) {
        // ---- wd transposing cvt: [E][I][H] f32 -> [E][H][I] fp16, 4 tiles/block ----
        float* tile = (float*)smem;   // 32*36 floats in dynamic smem
        int idx = blockIdx.x - GA_BLOCKS;
        int cg4 = idx & 15;            // group of 4 c-tiles over H (64 tiles total)
        int ry  = (idx >> 4) & 31;     // I/32 tiles
        int e   = idx >> 9;
        int r0  = ry * 32;
        size_t eo = (size_t)e * I_DIM * H_DIM;
        int lr = tid >> 3, lc = (tid & 7) * 4;
        int sc = tid >> 3, sr = (tid & 7) * 4;
#pragma unroll
        for (int j = 0; j < 4; j++) {
            int c0 = (cg4 * 4 + j) * 32;
            *(float4*)&tile[lr * 36 + lc] =
                *(const float4*)&wd_src[eo + (size_t)(r0 + lr) * H_DIM + c0 + lc];
            __syncthreads();
            uint2 v = pack4h(tile[sr * 36 + sc], tile[(sr+1) * 36 + sc],
                             tile[(sr+2) * 36 + sc], tile[(sr+3) * 36 + sc]);
            *(uint2*)&g_wd_h[eo + (size_t)(c0 + sc) * I_DIM + r0 + sr] = v;
            __syncthreads();
        }
        return;
    }

    int nx = blockIdx.x & 15;          // I/64 tiles
    int ny = (blockIdx.x >> 4) & 31;   // T/128 tiles
    int e  = blockIdx.x >> 9;
    int cnt = g_cnt[e];
    int m0  = ny * 128;
    if (m0 >= cnt) return;
    int n0   = nx * 64;
    int base = g_off[e];

    uint32_t sbase = (uint32_t)__cvta_generic_to_shared(smem);

    __shared__ int s_tok[128];
    if (tid < 128) {
        int m = m0 + tid;
        s_tok[tid] = g_slot_token[base + ((m < cnt) ? m : 0)];
    }
    __syncthreads();

    const __half* wgb = wgate + ((size_t)e * I_DIM + n0) * H_DIM;
    const __half* wub = wup   + ((size_t)e * I_DIM + n0) * H_DIM;

    int c8 = tid & 7, r32 = tid >> 3;

    const int NT = H_DIM / 64;  // 32

    auto load_stage = [&](int t, int s) {
        int k0 = t * 64;
        uint32_t ab = sbase + s * SLOT_BYTES;
        uint32_t gb = ab + A_BYTES;
        uint32_t ub = gb + BG_BYTES;
#pragma unroll
        for (int i = 0; i < 4; i++) {
            int r = r32 + i * 32;
            cpa16(ab + (uint32_t)(r * AH_STRIDE + c8 * 8) * 2u,
                  x + (size_t)s_tok[r] * H_DIM + k0 + c8 * 8);
        }
#pragma unroll
        for (int i = 0; i < 2; i++) {
            int r = r32 + i * 32;
            uint32_t so = (uint32_t)(r * AH_STRIDE + c8 * 8) * 2u;
            cpa16(gb + so, wgb + (size_t)r * H_DIM + k0 + c8 * 8);
            cpa16(ub + so, wub + (size_t)r * H_DIM + k0 + c8 * 8);
        }
        CP_COMMIT();
    };

    int wid = tid >> 5, lane = tid & 31;
    int wm = (wid & 3) * 32, wn = (wid >> 2) * 32;
    int gid = lane >> 2, tig = lane & 3;

    int a_row  = lane & 15, a_col = (lane >> 4) << 3;
    int b_rowo = ((lane >> 4) << 3) + (lane & 7);
    int b_colo = ((lane >> 3) & 1) << 3;

    float cg[2][4][4], cu[2][4][4];
#pragma unroll
    for (int i = 0; i < 2; i++)
#pragma unroll
        for (int j = 0; j < 4; j++)
#pragma unroll
            for (int q = 0; q < 4; q++) { cg[i][j][q] = 0.0f; cu[i][j][q] = 0.0f; }

    load_stage(0, 0);
    load_stage(1, 1);

    int sl = 2, sc = 0;
    for (int t = 0; t < NT; t++) {
        CP_WAIT(1);
        __syncthreads();
        if (t + 2 < NT) {
            load_stage(t + 2, sl);
            if (++sl == NSTAGE) sl = 0;
        } else {
            CP_COMMIT();
        }

        uint32_t sA = sbase + sc * SLOT_BYTES;
        uint32_t sG = sA + A_BYTES;
        uint32_t sU = sG + BG_BYTES;
        if (++sc == NSTAGE) sc = 0;

#pragma unroll
        for (int kf = 0; kf < 64; kf += 16) {
            uint32_t a[2][4], bg[4][2], bu[4][2];
#pragma unroll
            for (int mf = 0; mf < 2; mf++) {
                uint32_t addr = sA + (uint32_t)((wm + mf * 16 + a_row) * AH_STRIDE
                                                + kf + a_col) * 2u;
                ldsm4(a[mf][0], a[mf][1], a[mf][2], a[mf][3], addr);
            }
#pragma unroll
            for (int p = 0; p < 2; p++) {
                uint32_t so = (uint32_t)((wn + p * 16 + b_rowo) * AH_STRIDE
                                         + kf + b_colo) * 2u;
                ldsm4(bg[2*p][0], bg[2*p][1], bg[2*p+1][0], bg[2*p+1][1], sG + so);
                ldsm4(bu[2*p][0], bu[2*p][1], bu[2*p+1][0], bu[2*p+1][1], sU + so);
            }
#pragma unroll
            for (int mf = 0; mf < 2; mf++)
#pragma unroll
                for (int nf = 0; nf < 4; nf++) {
                    mma16(cg[mf][nf], a[mf], bg[nf]);
                    mma16(cu[mf][nf], a[mf], bu[nf]);
                }
        }
    }

#pragma unroll
    for (int mf = 0; mf < 2; mf++)
#pragma unroll
        for (int nf = 0; nf < 4; nf++) {
            int col = n0 + wn + nf * 8 + 2 * tig;
            int r1 = wm + mf * 16 + gid;
            int r2 = r1 + 8;
            int m1 = m0 + r1, m2 = m0 + r2;
            if (m1 < cnt) {
                __half2 v = __floats2half2_rn(silu(cg[mf][nf][0]) * cu[mf][nf][0],
                                              silu(cg[mf][nf][1]) * cu[mf][nf][1]);
                *(__half2*)&g_hbuf_h[(size_t)(base + m1) * I_DIM + col] = v;
            }
            if (m2 < cnt) {
                __half2 v = __floats2half2_rn(silu(cg[mf][nf][2]) * cu[mf][nf][2],
                                              silu(cg[mf][nf][3]) * cu[mf][nf][3]);
                *(__half2*)&g_hbuf_h[(size_t)(base + m2) * I_DIM + col] = v;
            }
        }
}

// ================= kernel 4: down GEMM weighted (fp16 mma, 3-stage) =================
__global__ __launch_bounds__(256, 2) void k_gemmB(const __half* __restrict__ wdown) {
    int e   = blockIdx.z;
    int cnt = g_cnt[e];
    int m0  = blockIdx.y * 128;
    if (m0 >= cnt) return;
    int n0   = blockIdx.x * 128;
    int base = g_off[e];
    int tid  = threadIdx.x;

    extern __shared__ __half smem[];
    uint32_t sbase = (uint32_t)__cvta_generic_to_shared(smem);

    const __half* wb = wdown + ((size_t)e * H_DIM + n0) * I_DIM;

    int c8 = tid & 7, r32 = tid >> 3;

    const int NT = I_DIM / 64;  // 16

    auto load_stage = [&](int t, int s) {
        int k0 = t * 64;
        uint32_t ab = sbase + s * SLOT_BYTES;
        uint32_t bb = ab + A_BYTES;
#pragma unroll
        for (int i = 0; i < 4; i++) {
            int r = r32 + i * 32;
            int m = m0 + r;
            int slot = base + ((m < cnt) ? m : (cnt - 1));
            cpa16(ab + (uint32_t)(r * AH_STRIDE + c8 * 8) * 2u,
                  &g_hbuf_h[(size_t)slot * I_DIM + k0 + c8 * 8]);
        }
#pragma unroll
        for (int i = 0; i < 4; i++) {
            int r = r32 + i * 32;
            cpa16(bb + (uint32_t)(r * AH_STRIDE + c8 * 8) * 2u,
                  wb + (size_t)r * I_DIM + k0 + c8 * 8);
        }
        CP_COMMIT();
    };

    int wid = tid >> 5, lane = tid & 31;
    int wm = (wid & 3) * 32, wn = (wid >> 2) * 64;
    int gid = lane >> 2, tig = lane & 3;

    int a_row  = lane & 15, a_col = (lane >> 4) << 3;
    int b_rowo = ((lane >> 4) << 3) + (lane & 7);
    int b_colo = ((lane >> 3) & 1) << 3;

    float cc[2][8][4];
#pragma unroll
    for (int i = 0; i < 2; i++)
#pragma unroll
        for (int j = 0; j < 8; j++)
#pragma unroll
            for (int q = 0; q < 4; q++) cc[i][j][q] = 0.0f;

    load_stage(0, 0);
    load_stage(1, 1);

    int sl = 2, sc = 0;
    for (int t = 0; t < NT; t++) {
        CP_WAIT(1);
        __syncthreads();
        if (t + 2 < NT) {
            load_stage(t + 2, sl);
            if (++sl == NSTAGE) sl = 0;
        } else {
            CP_COMMIT();
        }

        uint32_t sA = sbase + sc * SLOT_BYTES;
        uint32_t sB = sA + A_BYTES;
        if (++sc == NSTAGE) sc = 0;

#pragma unroll
        for (int kf = 0; kf < 64; kf += 16) {
            uint32_t a[2][4], b[8][2];
#pragma unroll
            for (int mf = 0; mf < 2; mf++) {
                uint32_t addr = sA + (uint32_t)((wm + mf * 16 + a_row) * AH_STRIDE
                                                + kf + a_col) * 2u;
                ldsm4(a[mf][0], a[mf][1], a[mf][2], a[mf][3], addr);
            }
#pragma unroll
            for (int p = 0; p < 4; p++) {
                uint32_t so = (uint32_t)((wn + p * 16 + b_rowo) * AH_STRIDE
                                         + kf + b_colo) * 2u;
                ldsm4(b[2*p][0], b[2*p][1], b[2*p+1][0], b[2*p+1][1], sB + so);
            }
#pragma unroll
            for (int mf = 0; mf < 2; mf++)
#pragma unroll
                for (int nf = 0; nf < 8; nf++) mma16(cc[mf][nf], a[mf], b[nf]);
        }
    }

#pragma unroll
    for (int mf = 0; mf < 2; mf++) {
        int r1 = wm + mf * 16 + gid;
        int r2 = r1 + 8;
        int m1 = m0 + r1, m2 = m0 + r2;
        float w1 = (m1 < cnt) ? g_slot_w[base + m1] : 0.0f;
        float w2 = (m2 < cnt) ? g_slot_w[base + m2] : 0.0f;
#pragma unroll
        for (int nf = 0; nf < 8; nf++) {
            int col = n0 + wn + nf * 8 + 2 * tig;
            if (m1 < cnt) {
                __half2 v = __floats2half2_rn(cc[mf][nf][0] * w1, cc[mf][nf][1] * w1);
                *(__half2*)&g_dbuf_h[(size_t)(base + m1) * H_DIM + col] = v;
            }
            if (m2 < cnt) {
                __half2 v = __floats2half2_rn(cc[mf][nf][2] * w2, cc[mf][nf][3] * w2);
                *(__half2*)&g_dbuf_h[(size_t)(base + m2) * H_DIM + col] = v;
            }
        }
    }
}

// ---------------- kernel 5: combine ----------------
__global__ void k_reduce(float* __restrict__ out) {
    int idx4 = blockIdx.x * blockDim.x + threadIdx.x;
    int t  = idx4 >> 9;
    int h4 = idx4 & 511;
    const int* ps = &g_pair2slot[t * TOPK];
    float4 s = make_float4(0.f, 0.f, 0.f, 0.f);
#pragma unroll
    for (int k = 0; k < TOPK; k++) {
        uint2 raw = *(const uint2*)&g_dbuf_h[(size_t)ps[k] * H_DIM + h4 * 4];
        __half2 p0 = *(__half2*)&raw.x;
        __half2 p1 = *(__half2*)&raw.y;
        float2 f0 = __half22float2(p0);
        float2 f1 = __half22float2(p1);
        s.x += f0.x; s.y += f0.y; s.z += f1.x; s.w += f1.y;
    }
    *(float4*)&out[(size_t)idx4 * 4] = s;
}

// ---------------- launch ----------------
extern "C" void kernel_launch(void* const* d_in, const int* in_sizes, int n_in,
                              void* d_out, int out_size) {
    const float* x  = (const float*)d_in[0];
    const float* gw = (const float*)d_in[1];
    const float* wg = (const float*)d_in[2];
    const float* wu = (const float*)d_in[3];
    const float* wd = (const float*)d_in[4];
    float* out = (float*)d_out;

    int write_ids = (out_size >= T_TOK * H_DIM + P_NUM) ? 1 : 0;

    const int smemG = NSTAGE * SLOT_BYTES;   // 110592 B -> 2 CTAs/SM
    cudaFuncSetAttribute(k_gemmA, cudaFuncAttributeMaxDynamicSharedMemorySize, smemG);
    cudaFuncSetAttribute(k_gemmB, cudaFuncAttributeMaxDynamicSharedMemorySize, smemG);

    int* cnt_p;
    cudaGetSymbolAddress((void**)&cnt_p, g_cnt);
    cudaMemsetAsync(cnt_p, 0, E_NUM * sizeof(int));

    __half* wg_h; __half* wu_h; __half* wd_h; __half* x_h;
    cudaGetSymbolAddress((void**)&wg_h, g_wg_h);
    cudaGetSymbolAddress((void**)&wu_h, g_wu_h);
    cudaGetSymbolAddress((void**)&wd_h, g_wd_h);
    cudaGetSymbolAddress((void**)&x_h,  g_x_h);

    // L2: router + x-cvt + wg/wu cvt, one launch
    k_pre<<<PRE_ROUTER_BLOCKS + 65536, 256>>>(x, gw, wg, wu, out, write_ids);

    // L3: scan + scatter
    k_scan_scatter<<<1, 1024>>>();

    // L4: gemmA (16384 gemm blocks) + wd cvt (16384 tail blocks)
    k_gemmA<<<GA_BLOCKS + WD_CVT_BLOCKS, 256, smemG>>>(x_h, wg_h, wu_h, wd);

    // L5: gemmB  <- ncu -s 5 target
    dim3 gb(H_DIM / 128, T_TOK / 128, E_NUM);
    k_gemmB<<<gb, 256, smemG>>>(wd_h);

    // L6: reduce
    k_reduce<<<(T_TOK * H_DIM / 4) / 256, 256>>>(out);
}